// round 2
// baseline (speedup 1.0000x reference)
#include <cuda_runtime.h>

#define NCLS   64
#define DIM    256
#define NROWS  65536
#define MTILE  256          // rows per block in main kernel
#define MAIN_THREADS 512    // 16 warps, each owns one m16 slice
#define MAIN_BLOCKS  512    // 131072 / 256
#define WPITCH 260          // padded W row pitch (floats) -> conflict-free B loads
#define FPITCH 36           // padded feat-chunk row pitch  -> conflict-free A loads

// ---------------- device scratch (no allocations allowed) ----------------
__device__ float  g_sum[2][NCLS][DIM];   // raw segment sums (src, trg)
__device__ float  g_cnt[2][NCLS];
__device__ double g_acc;
__device__ int    g_lstride;             // 1 = labels int32, 2 = labels int64

// ---------------- helpers ----------------
__device__ __forceinline__ unsigned f2tf32(float x) {
    unsigned r;
    asm("cvt.rna.tf32.f32 %0, %1;" : "=r"(r) : "f"(x));
    return r;
}

__device__ __forceinline__ void mma_tf32(float (&d)[4], const unsigned (&a)[4], const unsigned (&b)[2]) {
    asm volatile(
        "mma.sync.aligned.m16n8k8.row.col.f32.tf32.tf32.f32 "
        "{%0,%1,%2,%3}, {%4,%5,%6,%7}, {%8,%9}, {%0,%1,%2,%3};\n"
        : "+f"(d[0]), "+f"(d[1]), "+f"(d[2]), "+f"(d[3])
        : "r"(a[0]), "r"(a[1]), "r"(a[2]), "r"(a[3]),
          "r"(b[0]), "r"(b[1]));
}

__device__ __forceinline__ float qmax(float v) {
    v = fmaxf(v, __shfl_xor_sync(0xffffffffu, v, 1));
    v = fmaxf(v, __shfl_xor_sync(0xffffffffu, v, 2));
    return v;
}
__device__ __forceinline__ float qsum(float v) {
    v += __shfl_xor_sync(0xffffffffu, v, 1);
    v += __shfl_xor_sync(0xffffffffu, v, 2);
    return v;
}

// ---------------- kernel -1: detect label dtype (int32 vs int64) ----------
// Safe: reads only the first 512 bytes of a >=256KB buffer. If labels are
// int64 (values 0..63), every odd 32-bit word is 0. For genuine int32 labels
// the odds of 64 consecutive odd words all being 0 are (1/64)^64 ~ 0.
__global__ void k_detect(const int* __restrict__ lbl) {
    bool odd_zero = true;
    #pragma unroll
    for (int i = 0; i < 64; ++i) odd_zero &= (lbl[2 * i + 1] == 0);
    g_lstride = odd_zero ? 2 : 1;
}

// ---------------- kernel 0: zero scratch ----------------
__global__ void k_zero() {
    int idx = blockIdx.x * blockDim.x + threadIdx.x;   // 64*512 = 32768
    float* s = &g_sum[0][0][0];
    if (idx < 2 * NCLS * DIM) s[idx] = 0.f;
    if (idx < 2 * NCLS) (&g_cnt[0][0])[idx] = 0.f;
    if (idx == 0) g_acc = 0.0;
}

// ---------------- kernel 1: segment sums via smem bins ----------------
// grid 256 blocks (256 rows each), 256 threads (one per column), dyn smem 64KB
__global__ void k_segsum(const float* __restrict__ feat,
                         const int* __restrict__ lbl32, int which) {
    extern __shared__ float bins[];            // [64][256]
    __shared__ int cbin[NCLS];
    const int ls = g_lstride;
    int d = threadIdx.x;
    #pragma unroll
    for (int c = 0; c < NCLS; ++c) bins[c * DIM + d] = 0.f;
    if (d < NCLS) cbin[d] = 0;
    __syncthreads();

    int base = blockIdx.x * 256;
    for (int r = 0; r < 256; r += 4) {
        int c0 = lbl32[(base + r + 0) * ls] & 63;
        int c1 = lbl32[(base + r + 1) * ls] & 63;
        int c2 = lbl32[(base + r + 2) * ls] & 63;
        int c3 = lbl32[(base + r + 3) * ls] & 63;
        float f0 = feat[(size_t)(base + r + 0) * DIM + d];
        float f1 = feat[(size_t)(base + r + 1) * DIM + d];
        float f2 = feat[(size_t)(base + r + 2) * DIM + d];
        float f3 = feat[(size_t)(base + r + 3) * DIM + d];
        bins[c0 * DIM + d] += f0;
        bins[c1 * DIM + d] += f1;
        bins[c2 * DIM + d] += f2;
        bins[c3 * DIM + d] += f3;
        if (d == 0) { cbin[c0]++; cbin[c1]++; cbin[c2]++; cbin[c3]++; }
    }
    __syncthreads();
    #pragma unroll
    for (int c = 0; c < NCLS; ++c)
        atomicAdd(&g_sum[which][c][d], bins[c * DIM + d]);
    if (d < NCLS) atomicAdd(&g_cnt[which][d], (float)cbin[d]);
}

// ---------------- kernel 2: fused tf32 GEMM + softmax/KL ----------------
// Each block: 256 rows x 128 logit cols (cols 0..63 = S, 64..127 = T).
// 16 warps, each owns m16 x n128. Accum in registers, KL epilogue in-place.
#define SMEM_MAIN ((128 * WPITCH + MTILE * FPITCH) * 4 + 3 * NCLS * 4 + 16 * 4)

__global__ void __launch_bounds__(MAIN_THREADS, 1)
k_main(const float* __restrict__ src, const float* __restrict__ trg) {
    extern __shared__ unsigned char smem_raw[];
    unsigned* Ws  = (unsigned*)smem_raw;             // [128][WPITCH] tf32
    unsigned* Fs  = Ws + 128 * WPITCH;               // [256][FPITCH] tf32 (k-chunk)
    float*    inv = (float*)(Fs + MTILE * FPITCH);   // [3][64]
    float*    red = inv + 3 * NCLS;                  // [16]

    const int tid  = threadIdx.x;
    const int w    = tid >> 5;
    const int lane = tid & 31;
    const int g    = lane >> 2;
    const int t    = lane & 3;

    // stage W = [sum_s ; sum_t], converted to tf32
    for (int idx = tid; idx < 128 * DIM; idx += MAIN_THREADS) {
        int c = idx >> 8, k = idx & 255;
        float v = (c < NCLS) ? g_sum[0][c][k] : g_sum[1][c - NCLS][k];
        Ws[c * WPITCH + k] = f2tf32(v);
    }
    if (tid < NCLS) {
        float cs = g_cnt[0][tid], ct = g_cnt[1][tid];
        inv[tid]            = 1.f / cs;
        inv[NCLS + tid]     = 1.f / ct;
        inv[2 * NCLS + tid] = 1.f / (cs + ct);
    }

    // row tile for this block
    const float* fb = (blockIdx.x < 256) ? src : trg;
    const float4* gf = (const float4*)(fb + (size_t)(blockIdx.x & 255) * MTILE * DIM);

    float acc[16][4];
    #pragma unroll
    for (int n = 0; n < 16; ++n)
        #pragma unroll
        for (int j = 0; j < 4; ++j) acc[n][j] = 0.f;

    const int w16 = w * 16;

    for (int kc = 0; kc < 8; ++kc) {       // K chunks of 32
        __syncthreads();                    // protect Fs (and Ws/inv on first iter)
        #pragma unroll
        for (int i = 0; i < 4; ++i) {
            int f4 = tid + i * MAIN_THREADS;      // 0..2047
            int r  = f4 >> 3, q = f4 & 7;
            float4 v = gf[(size_t)r * 64 + kc * 8 + q];
            unsigned* dst = &Fs[r * FPITCH + q * 4];
            dst[0] = f2tf32(v.x); dst[1] = f2tf32(v.y);
            dst[2] = f2tf32(v.z); dst[3] = f2tf32(v.w);
        }
        __syncthreads();

        #pragma unroll
        for (int ks = 0; ks < 4; ++ks) {    // 4 x k8 steps per chunk
            int kk = ks * 8;
            unsigned a[4];
            a[0] = Fs[(w16 + g) * FPITCH + kk + t];
            a[1] = Fs[(w16 + g + 8) * FPITCH + kk + t];
            a[2] = Fs[(w16 + g) * FPITCH + kk + t + 4];
            a[3] = Fs[(w16 + g + 8) * FPITCH + kk + t + 4];
            int kglob = kc * 32 + kk;
            #pragma unroll
            for (int n = 0; n < 16; ++n) {
                unsigned b[2];
                b[0] = Ws[(n * 8 + g) * WPITCH + kglob + t];
                b[1] = Ws[(n * 8 + g) * WPITCH + kglob + t + 4];
                mma_tf32(acc[n], a, b);
            }
        }
    }

    // ---- fused epilogue: per-row 3 softmaxes + symmetrized KLs ----
    // lane owns classes c = 8n + 2t + j (n=0..7, j=0..1): S=acc[n][..], T=acc[n+8][..]
    float Jtot = 0.f;
    #pragma unroll
    for (int half = 0; half < 2; ++half) {  // rows (g) and (g+8)
        int j0 = half * 2;
        float mS = -1e30f, mT = -1e30f, mM = -1e30f;
        #pragma unroll
        for (int i = 0; i < 16; ++i) {
            int n = i >> 1, j = i & 1, c = n * 8 + 2 * t + j;
            float S = acc[n][j0 + j], T = acc[n + 8][j0 + j];
            float ps = S * inv[c];
            float pt = T * inv[NCLS + c];
            float pm = (S + T) * inv[2 * NCLS + c];
            mS = fmaxf(mS, ps); mT = fmaxf(mT, pt); mM = fmaxf(mM, pm);
        }
        mS = qmax(mS); mT = qmax(mT); mM = qmax(mM);

        float zS = 0.f, zT = 0.f, zM = 0.f;
        #pragma unroll
        for (int i = 0; i < 16; ++i) {
            int n = i >> 1, j = i & 1, c = n * 8 + 2 * t + j;
            float S = acc[n][j0 + j], T = acc[n + 8][j0 + j];
            float ps = S * inv[c];
            float pt = T * inv[NCLS + c];
            float pm = (S + T) * inv[2 * NCLS + c];
            zS += __expf(ps - mS); zT += __expf(pt - mT); zM += __expf(pm - mM);
        }
        zS = qsum(zS); zT = qsum(zT); zM = qsum(zM);
        float lseS = mS + __logf(zS);
        float lseT = mT + __logf(zT);
        float lseM = mM + __logf(zM);

        float J = 0.f;
        #pragma unroll
        for (int i = 0; i < 16; ++i) {
            int n = i >> 1, j = i & 1, c = n * 8 + 2 * t + j;
            float S = acc[n][j0 + j], T = acc[n + 8][j0 + j];
            float ls = S * inv[c] - lseS;
            float lt = T * inv[NCLS + c] - lseT;
            float lm = (S + T) * inv[2 * NCLS + c] - lseM;
            float es = __expf(ls), et = __expf(lt), em = __expf(lm);
            J += (et - es) * (lt - ls) + (em - es) * (lm - ls) + (em - et) * (lm - lt);
        }
        Jtot += qsum(J);   // replicated within quad
    }
    // sum across the 8 quads (quads already internally replicated)
    Jtot += __shfl_xor_sync(0xffffffffu, Jtot, 4);
    Jtot += __shfl_xor_sync(0xffffffffu, Jtot, 8);
    Jtot += __shfl_xor_sync(0xffffffffu, Jtot, 16);
    if (lane == 0) red[w] = Jtot;
    __syncthreads();
    if (tid == 0) {
        float bs = 0.f;
        #pragma unroll
        for (int i = 0; i < 16; ++i) bs += red[i];
        atomicAdd(&g_acc, (double)bs);
    }
}

// ---------------- kernel 3: finalize ----------------
__global__ void k_final(float* out) {
    // J terms above omit the 0.5 pair factor: scale = 0.5 / (3 * 2N * C)
    out[0] = (float)(g_acc * (0.5 / (3.0 * 131072.0 * 64.0)));
}

// ---------------- launch ----------------
extern "C" void kernel_launch(void* const* d_in, const int* in_sizes, int n_in,
                              void* d_out, int out_size) {
    const float* src = (const float*)d_in[0];
    const float* trg = (const float*)d_in[1];
    const int*   sl  = (const int*)d_in[2];
    const int*   tl  = (const int*)d_in[3];

    cudaFuncSetAttribute(k_segsum, cudaFuncAttributeMaxDynamicSharedMemorySize, 65536);
    cudaFuncSetAttribute(k_main,   cudaFuncAttributeMaxDynamicSharedMemorySize, SMEM_MAIN);

    k_detect<<<1, 1>>>(sl);
    k_zero<<<64, 512>>>();
    k_segsum<<<256, 256, 65536>>>(src, sl, 0);
    k_segsum<<<256, 256, 65536>>>(trg, tl, 1);
    k_main<<<MAIN_BLOCKS, MAIN_THREADS, SMEM_MAIN>>>(src, trg);
    k_final<<<1, 1>>>((float*)d_out);
}